// round 2
// baseline (speedup 1.0000x reference)
#include <cuda_runtime.h>
#include <cuda_fp16.h>

#define TSTEPS 30
#define BLOCK  128
#define NBATCH 262144

constexpr int   WTOT   = 2432;                       // prepped weight floats in smem
constexpr float NLOG2E = -1.4426950408889634f;

typedef unsigned long long u64;

// ---------- packed fp32x2 helpers (sm_103a FFMA2 path) ----------
__device__ __forceinline__ u64 ffma2(u64 a, u64 b, u64 c) {
    u64 d; asm("fma.rn.f32x2 %0, %1, %2, %3;" : "=l"(d) : "l"(a), "l"(b), "l"(c)); return d;
}
__device__ __forceinline__ u64 splat2(float v) {
    u64 d; asm("mov.b64 %0, {%1, %1};" : "=l"(d) : "f"(v)); return d;
}
__device__ __forceinline__ u64 pack2(float x, float y) {
    u64 d; asm("mov.b64 %0, {%1, %2};" : "=l"(d) : "f"(x), "f"(y)); return d;
}
__device__ __forceinline__ float2 unpack2(u64 v) {
    float2 r; asm("mov.b64 {%0, %1}, %2;" : "=f"(r.x), "=f"(r.y) : "l"(v)); return r;
}
__device__ __forceinline__ float ex2f(float x){ float r; asm("ex2.approx.f32 %0, %1;" : "=f"(r) : "f"(x)); return r; }
__device__ __forceinline__ float rcpf(float x){ float r; asm("rcp.approx.f32 %0, %1;" : "=f"(r) : "f"(x)); return r; }

__device__ __forceinline__ int comboOff(int c){ return c < 2 ? c*128 : 256 + (c-2)*272; }

union H4 { u64 u; __half2 h[2]; };
__device__ __forceinline__ u64 h4pack(__half2 a, __half2 b){ H4 t; t.h[0]=a; t.h[1]=b; return t.u; }

// ---------- one GRU timestep; weights live in smem (broadcast LDS), gates
// pre-scaled so sigmoid/tanh are ex2-based.
// slots: 0..4 r, 5..9 z, 10..14 n, 15 pad.
// r/z rows pre-scaled by -log2e: sig = rcp(1+2^a); n rows by -2log2e: tanh = 2*rcp(1+2^a)-1
template<int D>
__device__ __forceinline__ void gru_step(const float* __restrict__ wb,
                                         const float* xin, float* h)
{
    const float4* wih4 = (const float4*)wb;
    const float4* whh4 = (const float4*)(wb + 16*D);
    const float4* bi4  = (const float4*)(wb + 16*D + 80);
    const float4* bh4  = (const float4*)(wb + 16*D + 96);
    u64 gi[8], gh[8];
#pragma unroll
    for (int p = 0; p < 4; ++p) {
        float4 a = bi4[p]; gi[2*p]=pack2(a.x,a.y); gi[2*p+1]=pack2(a.z,a.w);
        float4 c = bh4[p]; gh[2*p]=pack2(c.x,c.y); gh[2*p+1]=pack2(c.z,c.w);
    }
#pragma unroll
    for (int k = 0; k < D; ++k) {
        u64 xs = splat2(xin[k]);
        float4 w0 = wih4[k*4+0], w1 = wih4[k*4+1], w2 = wih4[k*4+2], w3 = wih4[k*4+3];
        gi[0] = ffma2(pack2(w0.x,w0.y), xs, gi[0]);
        gi[1] = ffma2(pack2(w0.z,w0.w), xs, gi[1]);
        gi[2] = ffma2(pack2(w1.x,w1.y), xs, gi[2]);
        gi[3] = ffma2(pack2(w1.z,w1.w), xs, gi[3]);
        gi[4] = ffma2(pack2(w2.x,w2.y), xs, gi[4]);
        gi[5] = ffma2(pack2(w2.z,w2.w), xs, gi[5]);
        gi[6] = ffma2(pack2(w3.x,w3.y), xs, gi[6]);
        gi[7] = ffma2(pack2(w3.z,w3.w), xs, gi[7]);
    }
#pragma unroll
    for (int k = 0; k < 5; ++k) {
        u64 hs = splat2(h[k]);
        float4 w0 = whh4[k*4+0], w1 = whh4[k*4+1], w2 = whh4[k*4+2], w3 = whh4[k*4+3];
        gh[0] = ffma2(pack2(w0.x,w0.y), hs, gh[0]);
        gh[1] = ffma2(pack2(w0.z,w0.w), hs, gh[1]);
        gh[2] = ffma2(pack2(w1.x,w1.y), hs, gh[2]);
        gh[3] = ffma2(pack2(w1.z,w1.w), hs, gh[3]);
        gh[4] = ffma2(pack2(w2.x,w2.y), hs, gh[4]);
        gh[5] = ffma2(pack2(w2.z,w2.w), hs, gh[5]);
        gh[6] = ffma2(pack2(w3.x,w3.y), hs, gh[6]);
        gh[7] = ffma2(pack2(w3.z,w3.w), hs, gh[7]);
    }
    float g[16], q[16];
#pragma unroll
    for (int p = 0; p < 8; ++p) {
        float2 a = unpack2(gi[p]); g[2*p] = a.x; g[2*p+1] = a.y;
        float2 c = unpack2(gh[p]); q[2*p] = c.x; q[2*p+1] = c.y;
    }
#pragma unroll
    for (int u = 0; u < 5; ++u) {
        float r  = rcpf(1.f + ex2f(g[u]   + q[u]));
        float z  = rcpf(1.f + ex2f(g[5+u] + q[5+u]));
        float a  = fmaf(r, q[10+u], g[10+u]);
        float nn = fmaf(2.f, rcpf(1.f + ex2f(a)), -1.f);
        h[u] = nn + z*(h[u] - nn);
    }
}

// raw u64 triplet -> 10 floats (slots: fwd 0..4, bwd 5..9)
__device__ __forceinline__ void cvt_in(u64 r0, u64 r1, u64 r2, float* xin)
{
    H4 a, b, c; a.u = r0; b.u = r1; c.u = r2;
    float2 p0 = __half22float2(a.h[0]);
    float2 p1 = __half22float2(a.h[1]);
    float2 p2 = __half22float2(b.h[0]);
    float2 p3 = __half22float2(b.h[1]);
    float2 p4 = __half22float2(c.h[0]);
    float2 p5 = __half22float2(c.h[1]);
    xin[0]=p0.x; xin[1]=p0.y; xin[2]=p1.x; xin[3]=p1.y; xin[4]=p2.x;
    xin[5]=p3.x; xin[6]=p3.y; xin[7]=p4.x; xin[8]=p4.y; xin[9]=p5.x;
}

__global__ void __launch_bounds__(BLOCK, 4)
gru_kernel(const float* __restrict__ x,
           const float* __restrict__ wih0, const float* __restrict__ whh0,
           const float* __restrict__ bih0, const float* __restrict__ bhh0,
           const float* __restrict__ wihU, const float* __restrict__ whhU,
           const float* __restrict__ bihU, const float* __restrict__ bhhU,
           float* __restrict__ out)
{
    extern __shared__ float sw[];          // [WTOT] prepped weights only
    const int tid = threadIdx.x;

    // ---- cooperative weight prep: transpose, pad 15->16, pre-scale, merge biases ----
    for (int c = 0; c < 10; ++c) {
        int l = c >> 1, d = c & 1;
        int D = l ? 10 : 1;
        float* w = sw + comboOff(c);
        for (int i = tid; i < 16*D; i += BLOCK) {           // wihT[k][slot]
            int k = i >> 4, s = i & 15;
            float v = 0.f;
            if (s < 15) {
                float sc = (s < 10) ? NLOG2E : 2.f*NLOG2E;
                v = sc * (l == 0 ? wih0[d*15 + s]
                                 : wihU[(((l-1)*2 + d)*15 + s)*10 + k]);
            }
            w[i] = v;
        }
        float* wh = w + 16*D;
        for (int i = tid; i < 80; i += BLOCK) {             // whhT[k][slot]
            int k = i >> 4, s = i & 15;
            float v = 0.f;
            if (s < 15) {
                float sc = (s < 10) ? NLOG2E : 2.f*NLOG2E;
                v = sc * (l == 0 ? whh0[(d*15 + s)*5 + k]
                                 : whhU[(((l-1)*2 + d)*15 + s)*5 + k]);
            }
            wh[i] = v;
        }
        float* bg = wh + 80;                                // bias_gi
        for (int s = tid; s < 16; s += BLOCK) {
            float v = 0.f;
            if (s < 15) {
                float sc = (s < 10) ? NLOG2E : 2.f*NLOG2E;
                float bi = l == 0 ? bih0[d*15 + s] : bihU[((l-1)*2 + d)*15 + s];
                float bh = l == 0 ? bhh0[d*15 + s] : bhhU[((l-1)*2 + d)*15 + s];
                v = sc * (s < 10 ? (bi + bh) : bi);
            }
            bg[s] = v;
        }
        float* bh2 = bg + 16;                               // bias_gh (n-gate b_hh)
        for (int s = tid; s < 16; s += BLOCK) {
            float v = 0.f;
            if (s >= 10 && s < 15) {
                float bh = l == 0 ? bhh0[d*15 + s] : bhhU[((l-1)*2 + d)*15 + s];
                v = 2.f*NLOG2E * bh;
            }
            bh2[s] = v;
        }
    }
    __syncthreads();

    const int b = blockIdx.x * BLOCK + tid;
    const float* xrow = x + (size_t)b * TSTEPS;

    // thread-private local-memory (L2-resident) activation storage, fp16
    // mbuf entry e = t+1 (pads at both ends for prefetch): {f0..f3},{f4,_,b0,b1},{b2,b3,b4,_}
    u64 mbuf[(TSTEPS+2)*3];
    u64 fscr[TSTEPS*2];                    // fwd staging: {f0..f3},{f4,_,_,_}

    float h[5];
    const __half2 hz = __float2half2_rn(0.f);

    // ===== layer 0 (D=1): fwd -> fscr, bwd -> merge into mbuf =====
    {
        const float* wb = sw + comboOff(0);
#pragma unroll
        for (int u = 0; u < 5; ++u) h[u] = 0.f;
#pragma unroll 1
        for (int t = 0; t < TSTEPS; ++t) {
            float xin[1] = { xrow[t] };
            gru_step<1>(wb, xin, h);
            __half2 c0 = __floats2half2_rn(h[0], h[1]);
            __half2 c1 = __floats2half2_rn(h[2], h[3]);
            __half2 c2 = __floats2half2_rn(h[4], 0.f);
            fscr[t*2+0] = h4pack(c0, c1);
            fscr[t*2+1] = h4pack(c2, hz);
        }
    }
    {
        const float* wb = sw + comboOff(1);
#pragma unroll
        for (int u = 0; u < 5; ++u) h[u] = 0.f;
#pragma unroll 1
        for (int tt = 0; tt < TSTEPS; ++tt) {
            int t = TSTEPS-1-tt;
            float xin[1] = { xrow[t] };
            gru_step<1>(wb, xin, h);
            __half2 d0 = __floats2half2_rn(h[0], h[1]);
            __half2 d1 = __floats2half2_rn(h[2], h[3]);
            __half2 d2 = __floats2half2_rn(h[4], 0.f);
            H4 s0, s1; s0.u = fscr[t*2+0]; s1.u = fscr[t*2+1];
            int e = t+1;
            mbuf[e*3+0] = s0.u;
            mbuf[e*3+1] = h4pack(s1.h[0], d0);
            mbuf[e*3+2] = h4pack(d1, d2);
        }
    }

    // ===== layers 1..3: fwd stages into fscr, bwd overwrites mbuf in place =====
#pragma unroll 1
    for (int l = 1; l < 4; ++l) {
        {   // fwd (prefetch next entry)
            const float* wb = sw + comboOff(2*l);
#pragma unroll
            for (int u = 0; u < 5; ++u) h[u] = 0.f;
            u64 r0 = mbuf[1*3+0], r1 = mbuf[1*3+1], r2 = mbuf[1*3+2];
#pragma unroll 1
            for (int t = 0; t < TSTEPS; ++t) {
                u64 c0 = r0, c1 = r1, c2 = r2;
                int en = t+2;                      // next entry (<= TSTEPS+1, padded)
                r0 = mbuf[en*3+0]; r1 = mbuf[en*3+1]; r2 = mbuf[en*3+2];
                float xin[10]; cvt_in(c0, c1, c2, xin);
                gru_step<10>(wb, xin, h);
                __half2 c0h = __floats2half2_rn(h[0], h[1]);
                __half2 c1h = __floats2half2_rn(h[2], h[3]);
                __half2 c2h = __floats2half2_rn(h[4], 0.f);
                fscr[t*2+0] = h4pack(c0h, c1h);
                fscr[t*2+1] = h4pack(c2h, hz);
            }
        }
        {   // bwd (prefetch prev entry); after reading entry t, overwrite merged
            const float* wb = sw + comboOff(2*l+1);
#pragma unroll
            for (int u = 0; u < 5; ++u) h[u] = 0.f;
            u64 r0 = mbuf[TSTEPS*3+0], r1 = mbuf[TSTEPS*3+1], r2 = mbuf[TSTEPS*3+2];
#pragma unroll 1
            for (int tt = 0; tt < TSTEPS; ++tt) {
                int t = TSTEPS-1-tt;
                u64 c0 = r0, c1 = r1, c2 = r2;
                int ep = t;                        // prev entry (>= 0, padded)
                r0 = mbuf[ep*3+0]; r1 = mbuf[ep*3+1]; r2 = mbuf[ep*3+2];
                float xin[10]; cvt_in(c0, c1, c2, xin);
                gru_step<10>(wb, xin, h);
                __half2 d0 = __floats2half2_rn(h[0], h[1]);
                __half2 d1 = __floats2half2_rn(h[2], h[3]);
                __half2 d2 = __floats2half2_rn(h[4], 0.f);
                H4 s0, s1; s0.u = fscr[t*2+0]; s1.u = fscr[t*2+1];
                int e = t+1;
                mbuf[e*3+0] = s0.u;
                mbuf[e*3+1] = h4pack(s1.h[0], d0);
                mbuf[e*3+2] = h4pack(d1, d2);
            }
        }
    }

    // ===== layer 4: fwd full (keep final h only); bwd = ONE step at t=T-1 =====
    float hf[5];
    {
        const float* wb = sw + comboOff(8);
#pragma unroll
        for (int u = 0; u < 5; ++u) h[u] = 0.f;
        u64 r0 = mbuf[1*3+0], r1 = mbuf[1*3+1], r2 = mbuf[1*3+2];
#pragma unroll 1
        for (int t = 0; t < TSTEPS; ++t) {
            u64 c0 = r0, c1 = r1, c2 = r2;
            int en = t+2;
            r0 = mbuf[en*3+0]; r1 = mbuf[en*3+1]; r2 = mbuf[en*3+2];
            float xin[10]; cvt_in(c0, c1, c2, xin);
            gru_step<10>(wb, xin, h);
        }
#pragma unroll
        for (int u = 0; u < 5; ++u) hf[u] = h[u];
    }
    {
        const float* wb = sw + comboOff(9);
#pragma unroll
        for (int u = 0; u < 5; ++u) h[u] = 0.f;
        int e = TSTEPS;                           // entry for t = T-1
        float xin[10]; cvt_in(mbuf[e*3+0], mbuf[e*3+1], mbuf[e*3+2], xin);
        gru_step<10>(wb, xin, h);
    }

    float2* o2 = (float2*)(out + (size_t)b*10);
    o2[0] = make_float2(hf[0], hf[1]);
    o2[1] = make_float2(hf[2], hf[3]);
    o2[2] = make_float2(hf[4], h[0]);
    o2[3] = make_float2(h[1],  h[2]);
    o2[4] = make_float2(h[3],  h[4]);
}

extern "C" void kernel_launch(void* const* d_in, const int* in_sizes, int n_in,
                              void* d_out, int out_size)
{
    (void)in_sizes; (void)n_in; (void)out_size;
    const size_t smem = (size_t)WTOT*4;   // 9728 B: weights only
    cudaFuncSetAttribute(gru_kernel, cudaFuncAttributeMaxDynamicSharedMemorySize, (int)smem);
    gru_kernel<<<NBATCH/BLOCK, BLOCK, smem>>>(
        (const float*)d_in[0],
        (const float*)d_in[1], (const float*)d_in[2],
        (const float*)d_in[3], (const float*)d_in[4],
        (const float*)d_in[5], (const float*)d_in[6],
        (const float*)d_in[7], (const float*)d_in[8],
        (float*)d_out);
}

// round 3
// speedup vs baseline: 2.5602x; 2.5602x over previous
#include <cuda_runtime.h>
#include <cuda_fp16.h>

#define TSTEPS 30
#define BLOCK  64
#define NBATCH 262144

constexpr int   WTOT   = 2432;                       // prepped weight floats in smem
constexpr float NLOG2E = -1.4426950408889634f;

typedef unsigned long long u64;

// ---------- packed fp32x2 helpers (sm_103a FFMA2 path) ----------
__device__ __forceinline__ u64 ffma2(u64 a, u64 b, u64 c) {
    u64 d; asm("fma.rn.f32x2 %0, %1, %2, %3;" : "=l"(d) : "l"(a), "l"(b), "l"(c)); return d;
}
__device__ __forceinline__ u64 splat2(float v) {
    u64 d; asm("mov.b64 %0, {%1, %1};" : "=l"(d) : "f"(v)); return d;
}
__device__ __forceinline__ u64 pack2(float x, float y) {
    u64 d; asm("mov.b64 %0, {%1, %2};" : "=l"(d) : "f"(x), "f"(y)); return d;
}
__device__ __forceinline__ float2 unpack2(u64 v) {
    float2 r; asm("mov.b64 {%0, %1}, %2;" : "=f"(r.x), "=f"(r.y) : "l"(v)); return r;
}
__device__ __forceinline__ float ex2f(float x){ float r; asm("ex2.approx.f32 %0, %1;" : "=f"(r) : "f"(x)); return r; }
__device__ __forceinline__ float rcpf(float x){ float r; asm("rcp.approx.f32 %0, %1;" : "=f"(r) : "f"(x)); return r; }

__device__ __forceinline__ int comboOff(int c){ return c < 2 ? c*128 : 256 + (c-2)*272; }

union H4 { u64 u; __half2 h[2]; };
__device__ __forceinline__ u64 h4pack(__half2 a, __half2 b){ H4 t; t.h[0]=a; t.h[1]=b; return t.u; }

// ---------- per-direction constants: W_hh (5x16 pre-scaled) + biases in registers ----------
__device__ __forceinline__ void load_dir(const float* wbase, int D, u64* whhr, u64* bgi, u64* bgh)
{
    const float4* wh4 = (const float4*)(wbase + 16*D);
#pragma unroll
    for (int k = 0; k < 5; ++k)
#pragma unroll
        for (int qq = 0; qq < 4; ++qq) {
            float4 a = wh4[k*4+qq];
            whhr[k*8+qq*2+0] = pack2(a.x, a.y);
            whhr[k*8+qq*2+1] = pack2(a.z, a.w);
        }
    const float4* b4 = (const float4*)(wbase + 16*D + 80);
#pragma unroll
    for (int qq = 0; qq < 4; ++qq) { float4 a = b4[qq]; bgi[qq*2]=pack2(a.x,a.y); bgi[qq*2+1]=pack2(a.z,a.w); }
    const float4* b5 = (const float4*)(wbase + 16*D + 96);
#pragma unroll
    for (int qq = 0; qq < 4; ++qq) { float4 a = b5[qq]; bgh[qq*2]=pack2(a.x,a.y); bgh[qq*2+1]=pack2(a.z,a.w); }
}

// ---------- one GRU timestep: wih streamed from smem (broadcast LDS.128),
// W_hh + biases register-resident. Gates pre-scaled so sigmoid/tanh are ex2-based.
// slots: 0..4 r, 5..9 z, 10..14 n, 15 pad.
template<int D>
__device__ __forceinline__ void gru_step(const float4* __restrict__ wih4,
                                         const u64* whhr, const u64* bgi, const u64* bgh,
                                         const float* xin, float* h)
{
    u64 gi[8], gh[8];
#pragma unroll
    for (int p = 0; p < 8; ++p) { gi[p] = bgi[p]; gh[p] = bgh[p]; }
#pragma unroll
    for (int k = 0; k < D; ++k) {
        u64 xs = splat2(xin[k]);
        float4 w0 = wih4[k*4+0], w1 = wih4[k*4+1], w2 = wih4[k*4+2], w3 = wih4[k*4+3];
        gi[0] = ffma2(pack2(w0.x,w0.y), xs, gi[0]);
        gi[1] = ffma2(pack2(w0.z,w0.w), xs, gi[1]);
        gi[2] = ffma2(pack2(w1.x,w1.y), xs, gi[2]);
        gi[3] = ffma2(pack2(w1.z,w1.w), xs, gi[3]);
        gi[4] = ffma2(pack2(w2.x,w2.y), xs, gi[4]);
        gi[5] = ffma2(pack2(w2.z,w2.w), xs, gi[5]);
        gi[6] = ffma2(pack2(w3.x,w3.y), xs, gi[6]);
        gi[7] = ffma2(pack2(w3.z,w3.w), xs, gi[7]);
    }
#pragma unroll
    for (int k = 0; k < 5; ++k) {
        u64 hs = splat2(h[k]);
#pragma unroll
        for (int p = 0; p < 8; ++p) gh[p] = ffma2(whhr[k*8+p], hs, gh[p]);
    }
    float g[16], q[16];
#pragma unroll
    for (int p = 0; p < 8; ++p) {
        float2 a = unpack2(gi[p]); g[2*p] = a.x; g[2*p+1] = a.y;
        float2 c = unpack2(gh[p]); q[2*p] = c.x; q[2*p+1] = c.y;
    }
#pragma unroll
    for (int u = 0; u < 5; ++u) {
        float r  = rcpf(1.f + ex2f(g[u]   + q[u]));
        float z  = rcpf(1.f + ex2f(g[5+u] + q[5+u]));
        float a  = fmaf(r, q[10+u], g[10+u]);
        float nn = fmaf(2.f, rcpf(1.f + ex2f(a)), -1.f);
        h[u] = nn + z*(h[u] - nn);
    }
}

// fp16 u64 triplet -> 10 floats (slots: fwd 0..4, bwd 5..9)
__device__ __forceinline__ void cvt_in(u64 r0, u64 r1, u64 r2, float* xin)
{
    H4 a, b, c; a.u = r0; b.u = r1; c.u = r2;
    float2 p0 = __half22float2(a.h[0]);
    float2 p1 = __half22float2(a.h[1]);
    float2 p2 = __half22float2(b.h[0]);
    float2 p3 = __half22float2(b.h[1]);
    float2 p4 = __half22float2(c.h[0]);
    float2 p5 = __half22float2(c.h[1]);
    xin[0]=p0.x; xin[1]=p0.y; xin[2]=p1.x; xin[3]=p1.y; xin[4]=p2.x;
    xin[5]=p3.x; xin[6]=p3.y; xin[7]=p4.x; xin[8]=p4.y; xin[9]=p5.x;
}

// smem activation buffer: [T][3][BLOCK] u64, fp16-packed
// entry t: slot0={f0..f3}, slot1={f4,pad,b0,b1}, slot2={b2,b3,b4,pad}
#define BUF(t,p) buf[((t)*3+(p))*BLOCK + tid]

__global__ void __launch_bounds__(BLOCK, 4)
gru_kernel(const float* __restrict__ x,
           const float* __restrict__ wih0, const float* __restrict__ whh0,
           const float* __restrict__ bih0, const float* __restrict__ bhh0,
           const float* __restrict__ wihU, const float* __restrict__ whhU,
           const float* __restrict__ bihU, const float* __restrict__ bhhU,
           float* __restrict__ out)
{
    extern __shared__ float smem[];
    float* sw  = smem;                       // [WTOT] prepped weights
    u64*   buf = (u64*)(smem + WTOT);        // [T*3*BLOCK] fp16 activations
    const int tid = threadIdx.x;

    // ---- cooperative weight prep: transpose, pad 15->16, pre-scale, merge biases ----
    for (int c = 0; c < 10; ++c) {
        int l = c >> 1, d = c & 1;
        int D = l ? 10 : 1;
        float* w = sw + comboOff(c);
        for (int i = tid; i < 16*D; i += BLOCK) {           // wihT[k][slot]
            int k = i >> 4, s = i & 15;
            float v = 0.f;
            if (s < 15) {
                float sc = (s < 10) ? NLOG2E : 2.f*NLOG2E;
                v = sc * (l == 0 ? wih0[d*15 + s]
                                 : wihU[(((l-1)*2 + d)*15 + s)*10 + k]);
            }
            w[i] = v;
        }
        float* wh = w + 16*D;
        for (int i = tid; i < 80; i += BLOCK) {             // whhT[k][slot]
            int k = i >> 4, s = i & 15;
            float v = 0.f;
            if (s < 15) {
                float sc = (s < 10) ? NLOG2E : 2.f*NLOG2E;
                v = sc * (l == 0 ? whh0[(d*15 + s)*5 + k]
                                 : whhU[(((l-1)*2 + d)*15 + s)*5 + k]);
            }
            wh[i] = v;
        }
        float* bg = wh + 80;                                // bias_gi
        for (int s = tid; s < 16; s += BLOCK) {
            float v = 0.f;
            if (s < 15) {
                float sc = (s < 10) ? NLOG2E : 2.f*NLOG2E;
                float bi = l == 0 ? bih0[d*15 + s] : bihU[((l-1)*2 + d)*15 + s];
                float bh = l == 0 ? bhh0[d*15 + s] : bhhU[((l-1)*2 + d)*15 + s];
                v = sc * (s < 10 ? (bi + bh) : bi);
            }
            bg[s] = v;
        }
        float* bh2 = bg + 16;                               // bias_gh (n-gate b_hh)
        for (int s = tid; s < 16; s += BLOCK) {
            float v = 0.f;
            if (s >= 10 && s < 15) {
                float bh = l == 0 ? bhh0[d*15 + s] : bhhU[((l-1)*2 + d)*15 + s];
                v = 2.f*NLOG2E * bh;
            }
            bh2[s] = v;
        }
    }
    __syncthreads();
    // buffer is thread-private from here on; no further syncs needed

    const int b = blockIdx.x * BLOCK + tid;
    const float* xrow = x + (size_t)b * TSTEPS;

    u64 whhr[40], bgi[8], bgh[8];
    float h[5];
    const __half2 hz = __float2half2_rn(0.f);
    u64 fscr[TSTEPS*2];                     // local fwd staging: {f0..f3},{f4,0,0,0}

    // ===== layer 0 (D=1): fwd -> fscr, bwd -> merged write to smem buf =====
    {
        const float* w = sw + comboOff(0);
        load_dir(w, 1, whhr, bgi, bgh);
        const float4* wih4 = (const float4*)w;
#pragma unroll
        for (int u = 0; u < 5; ++u) h[u] = 0.f;
#pragma unroll 1
        for (int t = 0; t < TSTEPS; ++t) {
            float xin[1] = { xrow[t] };
            gru_step<1>(wih4, whhr, bgi, bgh, xin, h);
            fscr[t*2+0] = h4pack(__floats2half2_rn(h[0], h[1]), __floats2half2_rn(h[2], h[3]));
            fscr[t*2+1] = h4pack(__floats2half2_rn(h[4], 0.f), hz);
        }
    }
    {
        const float* w = sw + comboOff(1);
        load_dir(w, 1, whhr, bgi, bgh);
        const float4* wih4 = (const float4*)w;
#pragma unroll
        for (int u = 0; u < 5; ++u) h[u] = 0.f;
#pragma unroll 1
        for (int tt = 0; tt < TSTEPS; ++tt) {
            int t = TSTEPS-1-tt;
            float xin[1] = { xrow[t] };
            gru_step<1>(wih4, whhr, bgi, bgh, xin, h);
            __half2 d0 = __floats2half2_rn(h[0], h[1]);
            __half2 d1 = __floats2half2_rn(h[2], h[3]);
            __half2 d2 = __floats2half2_rn(h[4], 0.f);
            H4 s1; s1.u = fscr[t*2+1];
            BUF(t,0) = fscr[t*2+0];
            BUF(t,1) = h4pack(s1.h[0], d0);
            BUF(t,2) = h4pack(d1, d2);
        }
    }

    // ===== layers 1..3: fwd stages into fscr, bwd overwrites smem buf in place =====
#pragma unroll 1
    for (int l = 1; l < 4; ++l) {
        {   // fwd
            const float* w = sw + comboOff(2*l);
            load_dir(w, 10, whhr, bgi, bgh);
            const float4* wih4 = (const float4*)w;
#pragma unroll
            for (int u = 0; u < 5; ++u) h[u] = 0.f;
#pragma unroll 1
            for (int t = 0; t < TSTEPS; ++t) {
                float xin[10]; cvt_in(BUF(t,0), BUF(t,1), BUF(t,2), xin);
                gru_step<10>(wih4, whhr, bgi, bgh, xin, h);
                fscr[t*2+0] = h4pack(__floats2half2_rn(h[0], h[1]), __floats2half2_rn(h[2], h[3]));
                fscr[t*2+1] = h4pack(__floats2half2_rn(h[4], 0.f), hz);
            }
        }
        {   // bwd; after reading entry t, overwrite with merged fwd+bwd
            const float* w = sw + comboOff(2*l+1);
            load_dir(w, 10, whhr, bgi, bgh);
            const float4* wih4 = (const float4*)w;
#pragma unroll
            for (int u = 0; u < 5; ++u) h[u] = 0.f;
#pragma unroll 1
            for (int tt = 0; tt < TSTEPS; ++tt) {
                int t = TSTEPS-1-tt;
                float xin[10]; cvt_in(BUF(t,0), BUF(t,1), BUF(t,2), xin);
                gru_step<10>(wih4, whhr, bgi, bgh, xin, h);
                __half2 d0 = __floats2half2_rn(h[0], h[1]);
                __half2 d1 = __floats2half2_rn(h[2], h[3]);
                __half2 d2 = __floats2half2_rn(h[4], 0.f);
                H4 s1; s1.u = fscr[t*2+1];
                BUF(t,0) = fscr[t*2+0];
                BUF(t,1) = h4pack(s1.h[0], d0);
                BUF(t,2) = h4pack(d1, d2);
            }
        }
    }

    // ===== layer 4: fwd full (keep final h only); bwd = ONE step at t=T-1 =====
    float hf[5];
    {
        const float* w = sw + comboOff(8);
        load_dir(w, 10, whhr, bgi, bgh);
        const float4* wih4 = (const float4*)w;
#pragma unroll
        for (int u = 0; u < 5; ++u) h[u] = 0.f;
#pragma unroll 1
        for (int t = 0; t < TSTEPS; ++t) {
            float xin[10]; cvt_in(BUF(t,0), BUF(t,1), BUF(t,2), xin);
            gru_step<10>(wih4, whhr, bgi, bgh, xin, h);
        }
#pragma unroll
        for (int u = 0; u < 5; ++u) hf[u] = h[u];
    }
    {
        const float* w = sw + comboOff(9);
        load_dir(w, 10, whhr, bgi, bgh);
        const float4* wih4 = (const float4*)w;
#pragma unroll
        for (int u = 0; u < 5; ++u) h[u] = 0.f;
        float xin[10]; cvt_in(BUF(TSTEPS-1,0), BUF(TSTEPS-1,1), BUF(TSTEPS-1,2), xin);
        gru_step<10>(wih4, whhr, bgi, bgh, xin, h);
    }

    float2* o2 = (float2*)(out + (size_t)b*10);
    o2[0] = make_float2(hf[0], hf[1]);
    o2[1] = make_float2(hf[2], hf[3]);
    o2[2] = make_float2(hf[4], h[0]);
    o2[3] = make_float2(h[1],  h[2]);
    o2[4] = make_float2(h[3],  h[4]);
}

extern "C" void kernel_launch(void* const* d_in, const int* in_sizes, int n_in,
                              void* d_out, int out_size)
{
    (void)in_sizes; (void)n_in; (void)out_size;
    const size_t smem = (size_t)WTOT*4 + (size_t)TSTEPS*3*BLOCK*sizeof(u64); // 55,808 B -> 4 blocks/SM
    cudaFuncSetAttribute(gru_kernel, cudaFuncAttributeMaxDynamicSharedMemorySize, (int)smem);
    gru_kernel<<<NBATCH/BLOCK, BLOCK, smem>>>(
        (const float*)d_in[0],
        (const float*)d_in[1], (const float*)d_in[2],
        (const float*)d_in[3], (const float*)d_in[4],
        (const float*)d_in[5], (const float*)d_in[6],
        (const float*)d_in[7], (const float*)d_in[8],
        (float*)d_out);
}

// round 4
// speedup vs baseline: 3.7075x; 1.4481x over previous
#include <cuda_runtime.h>
#include <cuda_fp16.h>

#define TSTEPS 30
#define BLOCK  64
#define NBATCH 262144

constexpr int   WTOT   = 2432;                       // prepped weight floats in smem
constexpr float NLOG2E = -1.4426950408889634f;

typedef unsigned long long u64;
typedef unsigned int       u32;

// ---------- packed fp32x2 helpers (sm_103a FFMA2 path) ----------
__device__ __forceinline__ u64 ffma2(u64 a, u64 b, u64 c) {
    u64 d; asm("fma.rn.f32x2 %0, %1, %2, %3;" : "=l"(d) : "l"(a), "l"(b), "l"(c)); return d;
}
__device__ __forceinline__ u64 splat2(float v) {
    u64 d; asm("mov.b64 %0, {%1, %1};" : "=l"(d) : "f"(v)); return d;
}
__device__ __forceinline__ u64 pack2(float x, float y) {
    u64 d; asm("mov.b64 %0, {%1, %2};" : "=l"(d) : "f"(x), "f"(y)); return d;
}
__device__ __forceinline__ float2 unpack2(u64 v) {
    float2 r; asm("mov.b64 {%0, %1}, %2;" : "=f"(r.x), "=f"(r.y) : "l"(v)); return r;
}
__device__ __forceinline__ float ex2f(float x){ float r; asm("ex2.approx.f32 %0, %1;" : "=f"(r) : "f"(x)); return r; }
__device__ __forceinline__ float rcpf(float x){ float r; asm("rcp.approx.f32 %0, %1;" : "=f"(r) : "f"(x)); return r; }

__device__ __forceinline__ int comboOff(int c){ return c < 2 ? c*128 : 256 + (c-2)*272; }

union H4 { u64 u; __half2 h[2]; };
union H2 { u32 u; __half2 h; };
__device__ __forceinline__ u64 h4pack(__half2 a, __half2 b){ H4 t; t.h[0]=a; t.h[1]=b; return t.u; }

// Slot order (rz-merged layout): s=2u+g for gate g∈{r,z}, unit u (s<10);
// s=10..14 -> n-gate unit s-10; s=15 pad. r/z rows scaled by -log2e (gi+gh merged),
// n rows scaled by -2log2e (gi, gh kept separate).

// ---------- per-direction constants: W_hh (5x16) + biases in registers ----------
__device__ __forceinline__ void load_dir(const float* wbase, int D,
                                         u64* whhr, u64* bA, u64* bGn, u64* bHn)
{
    const float4* wh4 = (const float4*)(wbase + 16*D);
#pragma unroll
    for (int k = 0; k < 5; ++k)
#pragma unroll
        for (int qq = 0; qq < 4; ++qq) {
            float4 a = wh4[k*4+qq];
            whhr[k*8+qq*2+0] = pack2(a.x, a.y);
            whhr[k*8+qq*2+1] = pack2(a.z, a.w);
        }
    const float4* b4 = (const float4*)(wbase + 16*D + 80);   // gi-side bias
    float4 c0 = b4[0], c1 = b4[1], c2 = b4[2], c3 = b4[3];
    bA[0] = pack2(c0.x,c0.y); bA[1] = pack2(c0.z,c0.w);
    bA[2] = pack2(c1.x,c1.y); bA[3] = pack2(c1.z,c1.w);
    bA[4] = pack2(c2.x,c2.y);
    bGn[0] = pack2(c2.z,c2.w); bGn[1] = pack2(c3.x,c3.y); bGn[2] = pack2(c3.z,c3.w);
    const float4* b5 = (const float4*)(wbase + 16*D + 96);   // gh-side n bias
    float4 d2 = b5[2], d3 = b5[3];
    bHn[0] = pack2(d2.z,d2.w); bHn[1] = pack2(d3.x,d3.y); bHn[2] = pack2(d3.z,d3.w);
}

// ---------- one GRU timestep ----------
template<int D>
__device__ __forceinline__ void gru_step(const float4* __restrict__ wih4,
                                         const u64* whhr, const u64* bA,
                                         const u64* bGn, const u64* bHn,
                                         const float* xin, float* h)
{
    u64 A[5], Gn[3], Hn[3];
#pragma unroll
    for (int p = 0; p < 5; ++p) A[p] = bA[p];
#pragma unroll
    for (int p = 0; p < 3; ++p) { Gn[p] = bGn[p]; Hn[p] = bHn[p]; }
#pragma unroll
    for (int k = 0; k < D; ++k) {
        u64 xs = splat2(xin[k]);
        float4 w0 = wih4[k*4+0], w1 = wih4[k*4+1], w2 = wih4[k*4+2], w3 = wih4[k*4+3];
        A[0]  = ffma2(pack2(w0.x,w0.y), xs, A[0]);
        A[1]  = ffma2(pack2(w0.z,w0.w), xs, A[1]);
        A[2]  = ffma2(pack2(w1.x,w1.y), xs, A[2]);
        A[3]  = ffma2(pack2(w1.z,w1.w), xs, A[3]);
        A[4]  = ffma2(pack2(w2.x,w2.y), xs, A[4]);
        Gn[0] = ffma2(pack2(w2.z,w2.w), xs, Gn[0]);
        Gn[1] = ffma2(pack2(w3.x,w3.y), xs, Gn[1]);
        Gn[2] = ffma2(pack2(w3.z,w3.w), xs, Gn[2]);
    }
#pragma unroll
    for (int k = 0; k < 5; ++k) {
        u64 hs = splat2(h[k]);
        A[0]  = ffma2(whhr[k*8+0], hs, A[0]);
        A[1]  = ffma2(whhr[k*8+1], hs, A[1]);
        A[2]  = ffma2(whhr[k*8+2], hs, A[2]);
        A[3]  = ffma2(whhr[k*8+3], hs, A[3]);
        A[4]  = ffma2(whhr[k*8+4], hs, A[4]);
        Hn[0] = ffma2(whhr[k*8+5], hs, Hn[0]);
        Hn[1] = ffma2(whhr[k*8+6], hs, Hn[1]);
        Hn[2] = ffma2(whhr[k*8+7], hs, Hn[2]);
    }
    float gn[6], hn[6];
#pragma unroll
    for (int p = 0; p < 3; ++p) {
        float2 a = unpack2(Gn[p]); gn[2*p] = a.x; gn[2*p+1] = a.y;
        float2 c = unpack2(Hn[p]); hn[2*p] = c.x; hn[2*p+1] = c.y;
    }
#pragma unroll
    for (int u = 0; u < 5; ++u) {
        float2 rz = unpack2(A[u]);
        float r  = rcpf(1.f + ex2f(rz.x));
        float z  = rcpf(1.f + ex2f(rz.y));
        float a  = fmaf(r, hn[u], gn[u]);
        float nn = fmaf(2.f, rcpf(1.f + ex2f(a)), -1.f);
        h[u] = fmaf(z, h[u] - nn, nn);
    }
}

// fp16 triplet -> 10 floats (fwd 0..4, bwd 5..9)
__device__ __forceinline__ void cvt_in(u64 ra, u64 rb, u32 rc, float* xin)
{
    H4 a, b; H2 c; a.u = ra; b.u = rb; c.u = rc;
    float2 p0 = __half22float2(a.h[0]);
    float2 p1 = __half22float2(a.h[1]);
    float2 p2 = __half22float2(b.h[0]);
    float2 p3 = __half22float2(b.h[1]);
    float2 p4 = __half22float2(c.h);
    xin[0]=p0.x; xin[1]=p0.y; xin[2]=p1.x; xin[3]=p1.y; xin[4]=p2.x;
    xin[5]=p2.y; xin[6]=p3.x; xin[7]=p3.y; xin[8]=p4.x; xin[9]=p4.y;
}

__global__ void __launch_bounds__(BLOCK, 4)
gru_kernel(const float* __restrict__ x,
           const float* __restrict__ wih0, const float* __restrict__ whh0,
           const float* __restrict__ bih0, const float* __restrict__ bhh0,
           const float* __restrict__ wihU, const float* __restrict__ whhU,
           const float* __restrict__ bihU, const float* __restrict__ bhhU,
           float* __restrict__ out)
{
    extern __shared__ float smem[];
    float* sw   = smem;                                   // [2432]
    u64*   bufA = (u64*)(smem + WTOT);                    // [T*BLOCK] (f0..f3)
    u64*   bufB = bufA + TSTEPS*BLOCK;                    // [T*BLOCK] (f4,b0,b1,b2)
    u32*   bufC = (u32*)(bufB + TSTEPS*BLOCK);            // [T*BLOCK] (b3,b4)
    const int tid = threadIdx.x;

    // ---- cooperative weight prep: transpose to slot layout, pre-scale, merge biases ----
    for (int c = 0; c < 10; ++c) {
        int l = c >> 1, d = c & 1;
        int D = l ? 10 : 1;
        float* w = sw + comboOff(c);
        for (int i = tid; i < 16*D; i += BLOCK) {           // wihT[k][slot]
            int k = i >> 4, s = i & 15;
            float v = 0.f;
            if (s < 15) {
                int  j  = (s < 10) ? ((s & 1)*5 + (s >> 1)) : s;
                float sc = (s < 10) ? NLOG2E : 2.f*NLOG2E;
                v = sc * (l == 0 ? wih0[d*15 + j]
                                 : wihU[(((l-1)*2 + d)*15 + j)*10 + k]);
            }
            w[i] = v;
        }
        float* wh = w + 16*D;
        for (int i = tid; i < 80; i += BLOCK) {             // whhT[k][slot]
            int k = i >> 4, s = i & 15;
            float v = 0.f;
            if (s < 15) {
                int  j  = (s < 10) ? ((s & 1)*5 + (s >> 1)) : s;
                float sc = (s < 10) ? NLOG2E : 2.f*NLOG2E;
                v = sc * (l == 0 ? whh0[(d*15 + j)*5 + k]
                                 : whhU[(((l-1)*2 + d)*15 + j)*5 + k]);
            }
            wh[i] = v;
        }
        float* bg = wh + 80;                                // gi-side bias
        for (int s = tid; s < 16; s += BLOCK) {
            float v = 0.f;
            if (s < 15) {
                int  j  = (s < 10) ? ((s & 1)*5 + (s >> 1)) : s;
                float sc = (s < 10) ? NLOG2E : 2.f*NLOG2E;
                float bi = l == 0 ? bih0[d*15 + j] : bihU[((l-1)*2 + d)*15 + j];
                float bh = l == 0 ? bhh0[d*15 + j] : bhhU[((l-1)*2 + d)*15 + j];
                v = sc * (s < 10 ? (bi + bh) : bi);
            }
            bg[s] = v;
        }
        float* bh2 = bg + 16;                               // gh-side n bias
        for (int s = tid; s < 16; s += BLOCK) {
            float v = 0.f;
            if (s >= 10 && s < 15) {
                float bh = l == 0 ? bhh0[d*15 + s] : bhhU[((l-1)*2 + d)*15 + s];
                v = 2.f*NLOG2E * bh;
            }
            bh2[s] = v;
        }
    }
    __syncthreads();
    // buffer slots are thread-private from here on; no further syncs needed

    const int b = blockIdx.x * BLOCK + tid;
    const float* xrow = x + (size_t)b * TSTEPS;

    u64 whhr[40], bA[5], bGn[3], bHn[3];
    float h[5];
    u64 fscrA[TSTEPS];        // local: (f0..f3) fp16
    u32 fscrC[TSTEPS];        // local: (f4,pad) fp16

    // ===== layer 0 (D=1): fwd -> fscr, bwd -> merged write to smem buf =====
    {
        const float* w = sw + comboOff(0);
        load_dir(w, 1, whhr, bA, bGn, bHn);
        const float4* wih4 = (const float4*)w;
#pragma unroll
        for (int u = 0; u < 5; ++u) h[u] = 0.f;
#pragma unroll 1
        for (int t = 0; t < TSTEPS; ++t) {
            float xin[1] = { xrow[t] };
            gru_step<1>(wih4, whhr, bA, bGn, bHn, xin, h);
            fscrA[t] = h4pack(__floats2half2_rn(h[0], h[1]), __floats2half2_rn(h[2], h[3]));
            H2 fc; fc.h = __floats2half2_rn(h[4], 0.f); fscrC[t] = fc.u;
        }
    }
    {
        const float* w = sw + comboOff(1);
        load_dir(w, 1, whhr, bA, bGn, bHn);
        const float4* wih4 = (const float4*)w;
#pragma unroll
        for (int u = 0; u < 5; ++u) h[u] = 0.f;
#pragma unroll 1
        for (int tt = 0; tt < TSTEPS; ++tt) {
            int t = TSTEPS-1-tt;
            u64 fa = fscrA[t]; H2 fc; fc.u = fscrC[t];     // early load (cover latency)
            float xin[1] = { xrow[t] };
            gru_step<1>(wih4, whhr, bA, bGn, bHn, xin, h);
            bufA[t*BLOCK+tid] = fa;
            bufB[t*BLOCK+tid] = h4pack(__halves2half2(__low2half(fc.h), __float2half_rn(h[0])),
                                       __floats2half2_rn(h[1], h[2]));
            H2 oc; oc.h = __floats2half2_rn(h[3], h[4]);
            bufC[t*BLOCK+tid] = oc.u;
        }
    }

    // ===== layers 1..3: fwd stages into fscr, bwd overwrites smem buf in place =====
#pragma unroll 1
    for (int l = 1; l < 4; ++l) {
        {   // fwd
            const float* w = sw + comboOff(2*l);
            load_dir(w, 10, whhr, bA, bGn, bHn);
            const float4* wih4 = (const float4*)w;
#pragma unroll
            for (int u = 0; u < 5; ++u) h[u] = 0.f;
#pragma unroll 1
            for (int t = 0; t < TSTEPS; ++t) {
                float xin[10];
                cvt_in(bufA[t*BLOCK+tid], bufB[t*BLOCK+tid], bufC[t*BLOCK+tid], xin);
                gru_step<10>(wih4, whhr, bA, bGn, bHn, xin, h);
                fscrA[t] = h4pack(__floats2half2_rn(h[0], h[1]), __floats2half2_rn(h[2], h[3]));
                H2 fc; fc.h = __floats2half2_rn(h[4], 0.f); fscrC[t] = fc.u;
            }
        }
        {   // bwd; fscr loaded at top of step (~full step of latency cover)
            const float* w = sw + comboOff(2*l+1);
            load_dir(w, 10, whhr, bA, bGn, bHn);
            const float4* wih4 = (const float4*)w;
#pragma unroll
            for (int u = 0; u < 5; ++u) h[u] = 0.f;
#pragma unroll 1
            for (int tt = 0; tt < TSTEPS; ++tt) {
                int t = TSTEPS-1-tt;
                u64 fa = fscrA[t]; H2 fc; fc.u = fscrC[t];
                float xin[10];
                cvt_in(bufA[t*BLOCK+tid], bufB[t*BLOCK+tid], bufC[t*BLOCK+tid], xin);
                gru_step<10>(wih4, whhr, bA, bGn, bHn, xin, h);
                bufA[t*BLOCK+tid] = fa;
                bufB[t*BLOCK+tid] = h4pack(__halves2half2(__low2half(fc.h), __float2half_rn(h[0])),
                                           __floats2half2_rn(h[1], h[2]));
                H2 oc; oc.h = __floats2half2_rn(h[3], h[4]);
                bufC[t*BLOCK+tid] = oc.u;
            }
        }
    }

    // ===== layer 4: fwd full (keep final h only); bwd = ONE step at t=T-1 =====
    float hf[5];
    {
        const float* w = sw + comboOff(8);
        load_dir(w, 10, whhr, bA, bGn, bHn);
        const float4* wih4 = (const float4*)w;
#pragma unroll
        for (int u = 0; u < 5; ++u) h[u] = 0.f;
#pragma unroll 1
        for (int t = 0; t < TSTEPS; ++t) {
            float xin[10];
            cvt_in(bufA[t*BLOCK+tid], bufB[t*BLOCK+tid], bufC[t*BLOCK+tid], xin);
            gru_step<10>(wih4, whhr, bA, bGn, bHn, xin, h);
        }
#pragma unroll
        for (int u = 0; u < 5; ++u) hf[u] = h[u];
    }
    {
        const float* w = sw + comboOff(9);
        load_dir(w, 10, whhr, bA, bGn, bHn);
        const float4* wih4 = (const float4*)w;
#pragma unroll
        for (int u = 0; u < 5; ++u) h[u] = 0.f;
        float xin[10];
        int t = TSTEPS-1;
        cvt_in(bufA[t*BLOCK+tid], bufB[t*BLOCK+tid], bufC[t*BLOCK+tid], xin);
        gru_step<10>(wih4, whhr, bA, bGn, bHn, xin, h);
    }

    float2* o2 = (float2*)(out + (size_t)b*10);
    o2[0] = make_float2(hf[0], hf[1]);
    o2[1] = make_float2(hf[2], hf[3]);
    o2[2] = make_float2(hf[4], h[0]);
    o2[3] = make_float2(h[1],  h[2]);
    o2[4] = make_float2(h[3],  h[4]);
}

extern "C" void kernel_launch(void* const* d_in, const int* in_sizes, int n_in,
                              void* d_out, int out_size)
{
    (void)in_sizes; (void)n_in; (void)out_size;
    // 9728 (weights) + 30*64*(8+8+4) = 9728 + 38400 = 48128 B -> 4 blocks/SM, L1D ~36 KB
    const size_t smem = (size_t)WTOT*4 + (size_t)TSTEPS*BLOCK*(8+8+4);
    cudaFuncSetAttribute(gru_kernel, cudaFuncAttributeMaxDynamicSharedMemorySize, (int)smem);
    gru_kernel<<<NBATCH/BLOCK, BLOCK, smem>>>(
        (const float*)d_in[0],
        (const float*)d_in[1], (const float*)d_in[2],
        (const float*)d_in[3], (const float*)d_in[4],
        (const float*)d_in[5], (const float*)d_in[6],
        (const float*)d_in[7], (const float*)d_in[8],
        (float*)d_out);
}

// round 5
// speedup vs baseline: 4.8166x; 1.2992x over previous
#include <cuda_runtime.h>
#include <cuda_fp16.h>

#define TSTEPS 30
#define BLOCK  64
#define NBATCH 262144

constexpr int WTOT = 2432;                       // prepped weight floats in smem

typedef unsigned long long u64;
typedef unsigned int       u32;

// ---------- packed fp32x2 helpers (sm_103a FFMA2 path) ----------
__device__ __forceinline__ u64 ffma2(u64 a, u64 b, u64 c) {
    u64 d; asm("fma.rn.f32x2 %0, %1, %2, %3;" : "=l"(d) : "l"(a), "l"(b), "l"(c)); return d;
}
__device__ __forceinline__ u64 splat2(float v) {
    u64 d; asm("mov.b64 %0, {%1, %1};" : "=l"(d) : "f"(v)); return d;
}
__device__ __forceinline__ u64 pack2(float x, float y) {
    u64 d; asm("mov.b64 %0, {%1, %2};" : "=l"(d) : "f"(x), "f"(y)); return d;
}
__device__ __forceinline__ float2 unpack2(u64 v) {
    float2 r; asm("mov.b64 {%0, %1}, %2;" : "=f"(r.x), "=f"(r.y) : "l"(v)); return r;
}
__device__ __forceinline__ float tanhfast(float x){ float r; asm("tanh.approx.f32 %0, %1;" : "=f"(r) : "f"(x)); return r; }

__device__ __forceinline__ int comboOff(int c){ return c < 2 ? c*128 : 256 + (c-2)*272; }

union H4 { u64 u; __half2 h[2]; };
union H2 { u32 u; __half2 h; };
__device__ __forceinline__ u64 h4pack(__half2 a, __half2 b){ H4 t; t.h[0]=a; t.h[1]=b; return t.u; }

// Slot order (rz-merged layout): s=2u+g for gate g in {r,z}, unit u (s<10);
// s=10..14 -> n-gate unit s-10; s=15 pad.
// r/z rows scaled by 0.5 (gi+gh merged): sig(v) = 0.5 + 0.5*tanh(v/2)
// n rows unscaled (gi, gh separate): n = tanh(gn + r*hn)

// ---------- per-direction constants: W_hh (5x16) + biases in registers ----------
__device__ __forceinline__ void load_dir(const float* wbase, int D,
                                         u64* whhr, u64* bA, u64* bGn, u64* bHn)
{
    const float4* wh4 = (const float4*)(wbase + 16*D);
#pragma unroll
    for (int k = 0; k < 5; ++k)
#pragma unroll
        for (int qq = 0; qq < 4; ++qq) {
            float4 a = wh4[k*4+qq];
            whhr[k*8+qq*2+0] = pack2(a.x, a.y);
            whhr[k*8+qq*2+1] = pack2(a.z, a.w);
        }
    const float4* b4 = (const float4*)(wbase + 16*D + 80);   // gi-side bias
    float4 c0 = b4[0], c1 = b4[1], c2 = b4[2], c3 = b4[3];
    bA[0] = pack2(c0.x,c0.y); bA[1] = pack2(c0.z,c0.w);
    bA[2] = pack2(c1.x,c1.y); bA[3] = pack2(c1.z,c1.w);
    bA[4] = pack2(c2.x,c2.y);
    bGn[0] = pack2(c2.z,c2.w); bGn[1] = pack2(c3.x,c3.y); bGn[2] = pack2(c3.z,c3.w);
    const float4* b5 = (const float4*)(wbase + 16*D + 96);   // gh-side n bias
    float4 d2 = b5[2], d3 = b5[3];
    bHn[0] = pack2(d2.z,d2.w); bHn[1] = pack2(d3.x,d3.y); bHn[2] = pack2(d3.z,d3.w);
}

// ---------- one GRU timestep ----------
template<int D>
__device__ __forceinline__ void gru_step(const float4* __restrict__ wih4,
                                         const u64* whhr, const u64* bA,
                                         const u64* bGn, const u64* bHn,
                                         const float* xin, float* h)
{
    u64 A[5], Gn[3], Hn[3];
#pragma unroll
    for (int p = 0; p < 5; ++p) A[p] = bA[p];
#pragma unroll
    for (int p = 0; p < 3; ++p) { Gn[p] = bGn[p]; Hn[p] = bHn[p]; }
#pragma unroll
    for (int k = 0; k < D; ++k) {
        u64 xs = splat2(xin[k]);
        float4 w0 = wih4[k*4+0], w1 = wih4[k*4+1], w2 = wih4[k*4+2], w3 = wih4[k*4+3];
        A[0]  = ffma2(pack2(w0.x,w0.y), xs, A[0]);
        A[1]  = ffma2(pack2(w0.z,w0.w), xs, A[1]);
        A[2]  = ffma2(pack2(w1.x,w1.y), xs, A[2]);
        A[3]  = ffma2(pack2(w1.z,w1.w), xs, A[3]);
        A[4]  = ffma2(pack2(w2.x,w2.y), xs, A[4]);
        Gn[0] = ffma2(pack2(w2.z,w2.w), xs, Gn[0]);
        Gn[1] = ffma2(pack2(w3.x,w3.y), xs, Gn[1]);
        Gn[2] = ffma2(pack2(w3.z,w3.w), xs, Gn[2]);
    }
#pragma unroll
    for (int k = 0; k < 5; ++k) {
        u64 hs = splat2(h[k]);
        A[0]  = ffma2(whhr[k*8+0], hs, A[0]);
        A[1]  = ffma2(whhr[k*8+1], hs, A[1]);
        A[2]  = ffma2(whhr[k*8+2], hs, A[2]);
        A[3]  = ffma2(whhr[k*8+3], hs, A[3]);
        A[4]  = ffma2(whhr[k*8+4], hs, A[4]);
        Hn[0] = ffma2(whhr[k*8+5], hs, Hn[0]);
        Hn[1] = ffma2(whhr[k*8+6], hs, Hn[1]);
        Hn[2] = ffma2(whhr[k*8+7], hs, Hn[2]);
    }
    float gn[6], hn[6];
#pragma unroll
    for (int p = 0; p < 3; ++p) {
        float2 a = unpack2(Gn[p]); gn[2*p] = a.x; gn[2*p+1] = a.y;
        float2 c = unpack2(Hn[p]); hn[2*p] = c.x; hn[2*p+1] = c.y;
    }
#pragma unroll
    for (int u = 0; u < 5; ++u) {
        float2 rz = unpack2(A[u]);                   // pre-scaled by 0.5
        float r  = fmaf(0.5f, tanhfast(rz.x), 0.5f);
        float z  = fmaf(0.5f, tanhfast(rz.y), 0.5f);
        float nn = tanhfast(fmaf(r, hn[u], gn[u]));
        h[u] = fmaf(z, h[u] - nn, nn);
    }
}

// fp16 triplet -> 10 floats (fwd 0..4, bwd 5..9)
__device__ __forceinline__ void cvt_in(u64 ra, u64 rb, u32 rc, float* xin)
{
    H4 a, b; H2 c; a.u = ra; b.u = rb; c.u = rc;
    float2 p0 = __half22float2(a.h[0]);
    float2 p1 = __half22float2(a.h[1]);
    float2 p2 = __half22float2(b.h[0]);
    float2 p3 = __half22float2(b.h[1]);
    float2 p4 = __half22float2(c.h);
    xin[0]=p0.x; xin[1]=p0.y; xin[2]=p1.x; xin[3]=p1.y; xin[4]=p2.x;
    xin[5]=p2.y; xin[6]=p3.x; xin[7]=p3.y; xin[8]=p4.x; xin[9]=p4.y;
}

__global__ void __launch_bounds__(BLOCK, 4)
gru_kernel(const float* __restrict__ x,
           const float* __restrict__ wih0, const float* __restrict__ whh0,
           const float* __restrict__ bih0, const float* __restrict__ bhh0,
           const float* __restrict__ wihU, const float* __restrict__ whhU,
           const float* __restrict__ bihU, const float* __restrict__ bhhU,
           float* __restrict__ out)
{
    extern __shared__ float smem[];
    float* sw   = smem;                                   // [2432]
    u64*   bufA = (u64*)(smem + WTOT);                    // [T*BLOCK] (f0..f3)
    u64*   bufB = bufA + TSTEPS*BLOCK;                    // [T*BLOCK] (f4,b0,b1,b2)
    u32*   bufC = (u32*)(bufB + TSTEPS*BLOCK);            // [T*BLOCK] (b3,b4)
    const int tid = threadIdx.x;

    // ---- cooperative weight prep: transpose to slot layout, pre-scale, merge biases ----
    for (int c = 0; c < 10; ++c) {
        int l = c >> 1, d = c & 1;
        int D = l ? 10 : 1;
        float* w = sw + comboOff(c);
        for (int i = tid; i < 16*D; i += BLOCK) {           // wihT[k][slot]
            int k = i >> 4, s = i & 15;
            float v = 0.f;
            if (s < 15) {
                int  j  = (s < 10) ? ((s & 1)*5 + (s >> 1)) : s;
                float sc = (s < 10) ? 0.5f : 1.0f;
                v = sc * (l == 0 ? wih0[d*15 + j]
                                 : wihU[(((l-1)*2 + d)*15 + j)*10 + k]);
            }
            w[i] = v;
        }
        float* wh = w + 16*D;
        for (int i = tid; i < 80; i += BLOCK) {             // whhT[k][slot]
            int k = i >> 4, s = i & 15;
            float v = 0.f;
            if (s < 15) {
                int  j  = (s < 10) ? ((s & 1)*5 + (s >> 1)) : s;
                float sc = (s < 10) ? 0.5f : 1.0f;
                v = sc * (l == 0 ? whh0[(d*15 + j)*5 + k]
                                 : whhU[(((l-1)*2 + d)*15 + j)*5 + k]);
            }
            wh[i] = v;
        }
        float* bg = wh + 80;                                // gi-side bias
        for (int s = tid; s < 16; s += BLOCK) {
            float v = 0.f;
            if (s < 15) {
                int  j  = (s < 10) ? ((s & 1)*5 + (s >> 1)) : s;
                float sc = (s < 10) ? 0.5f : 1.0f;
                float bi = l == 0 ? bih0[d*15 + j] : bihU[((l-1)*2 + d)*15 + j];
                float bh = l == 0 ? bhh0[d*15 + j] : bhhU[((l-1)*2 + d)*15 + j];
                v = sc * (s < 10 ? (bi + bh) : bi);
            }
            bg[s] = v;
        }
        float* bh2 = bg + 16;                               // gh-side n bias
        for (int s = tid; s < 16; s += BLOCK) {
            float v = 0.f;
            if (s >= 10 && s < 15) {
                float bh = l == 0 ? bhh0[d*15 + s] : bhhU[((l-1)*2 + d)*15 + s];
                v = bh;
            }
            bh2[s] = v;
        }
    }
    __syncthreads();
    // buffer slots are thread-private from here on; no further syncs needed

    const int b = blockIdx.x * BLOCK + tid;
    const float* xrow = x + (size_t)b * TSTEPS;

    u64 whhr[40], bA[5], bGn[3], bHn[3];
    float h[5];
    u64 fscrA[TSTEPS];        // local: (f0..f3) fp16
    u32 fscrC[TSTEPS];        // local: (f4,pad) fp16

    // ===== layer 0 (D=1): fwd -> fscr, bwd -> merged write to smem buf =====
    {
        const float* w = sw + comboOff(0);
        load_dir(w, 1, whhr, bA, bGn, bHn);
        const float4* wih4 = (const float4*)w;
#pragma unroll
        for (int u = 0; u < 5; ++u) h[u] = 0.f;
#pragma unroll 1
        for (int t = 0; t < TSTEPS; ++t) {
            float xin[1] = { xrow[t] };
            gru_step<1>(wih4, whhr, bA, bGn, bHn, xin, h);
            fscrA[t] = h4pack(__floats2half2_rn(h[0], h[1]), __floats2half2_rn(h[2], h[3]));
            H2 fc; fc.h = __floats2half2_rn(h[4], 0.f); fscrC[t] = fc.u;
        }
    }
    {
        const float* w = sw + comboOff(1);
        load_dir(w, 1, whhr, bA, bGn, bHn);
        const float4* wih4 = (const float4*)w;
#pragma unroll
        for (int u = 0; u < 5; ++u) h[u] = 0.f;
#pragma unroll 1
        for (int tt = 0; tt < TSTEPS; ++tt) {
            int t = TSTEPS-1-tt;
            u64 fa = fscrA[t]; H2 fc; fc.u = fscrC[t];     // early load (cover latency)
            float xin[1] = { xrow[t] };
            gru_step<1>(wih4, whhr, bA, bGn, bHn, xin, h);
            bufA[t*BLOCK+tid] = fa;
            bufB[t*BLOCK+tid] = h4pack(__halves2half2(__low2half(fc.h), __float2half_rn(h[0])),
                                       __floats2half2_rn(h[1], h[2]));
            H2 oc; oc.h = __floats2half2_rn(h[3], h[4]);
            bufC[t*BLOCK+tid] = oc.u;
        }
    }

    // ===== layers 1..3: fwd stages into fscr, bwd overwrites smem buf in place =====
#pragma unroll 1
    for (int l = 1; l < 4; ++l) {
        {   // fwd
            const float* w = sw + comboOff(2*l);
            load_dir(w, 10, whhr, bA, bGn, bHn);
            const float4* wih4 = (const float4*)w;
#pragma unroll
            for (int u = 0; u < 5; ++u) h[u] = 0.f;
#pragma unroll 1
            for (int t = 0; t < TSTEPS; ++t) {
                float xin[10];
                cvt_in(bufA[t*BLOCK+tid], bufB[t*BLOCK+tid], bufC[t*BLOCK+tid], xin);
                gru_step<10>(wih4, whhr, bA, bGn, bHn, xin, h);
                fscrA[t] = h4pack(__floats2half2_rn(h[0], h[1]), __floats2half2_rn(h[2], h[3]));
                H2 fc; fc.h = __floats2half2_rn(h[4], 0.f); fscrC[t] = fc.u;
            }
        }
        {   // bwd; fscr loaded at top of step (~full step of latency cover)
            const float* w = sw + comboOff(2*l+1);
            load_dir(w, 10, whhr, bA, bGn, bHn);
            const float4* wih4 = (const float4*)w;
#pragma unroll
            for (int u = 0; u < 5; ++u) h[u] = 0.f;
#pragma unroll 1
            for (int tt = 0; tt < TSTEPS; ++tt) {
                int t = TSTEPS-1-tt;
                u64 fa = fscrA[t]; H2 fc; fc.u = fscrC[t];
                float xin[10];
                cvt_in(bufA[t*BLOCK+tid], bufB[t*BLOCK+tid], bufC[t*BLOCK+tid], xin);
                gru_step<10>(wih4, whhr, bA, bGn, bHn, xin, h);
                bufA[t*BLOCK+tid] = fa;
                bufB[t*BLOCK+tid] = h4pack(__halves2half2(__low2half(fc.h), __float2half_rn(h[0])),
                                           __floats2half2_rn(h[1], h[2]));
                H2 oc; oc.h = __floats2half2_rn(h[3], h[4]);
                bufC[t*BLOCK+tid] = oc.u;
            }
        }
    }

    // ===== layer 4: fwd full (keep final h only); bwd = ONE step at t=T-1 =====
    float hf[5];
    {
        const float* w = sw + comboOff(8);
        load_dir(w, 10, whhr, bA, bGn, bHn);
        const float4* wih4 = (const float4*)w;
#pragma unroll
        for (int u = 0; u < 5; ++u) h[u] = 0.f;
#pragma unroll 1
        for (int t = 0; t < TSTEPS; ++t) {
            float xin[10];
            cvt_in(bufA[t*BLOCK+tid], bufB[t*BLOCK+tid], bufC[t*BLOCK+tid], xin);
            gru_step<10>(wih4, whhr, bA, bGn, bHn, xin, h);
        }
#pragma unroll
        for (int u = 0; u < 5; ++u) hf[u] = h[u];
    }
    {
        const float* w = sw + comboOff(9);
        load_dir(w, 10, whhr, bA, bGn, bHn);
        const float4* wih4 = (const float4*)w;
#pragma unroll
        for (int u = 0; u < 5; ++u) h[u] = 0.f;
        float xin[10];
        int t = TSTEPS-1;
        cvt_in(bufA[t*BLOCK+tid], bufB[t*BLOCK+tid], bufC[t*BLOCK+tid], xin);
        gru_step<10>(wih4, whhr, bA, bGn, bHn, xin, h);
    }

    float2* o2 = (float2*)(out + (size_t)b*10);
    o2[0] = make_float2(hf[0], hf[1]);
    o2[1] = make_float2(hf[2], hf[3]);
    o2[2] = make_float2(hf[4], h[0]);
    o2[3] = make_float2(h[1],  h[2]);
    o2[4] = make_float2(h[3],  h[4]);
}

extern "C" void kernel_launch(void* const* d_in, const int* in_sizes, int n_in,
                              void* d_out, int out_size)
{
    (void)in_sizes; (void)n_in; (void)out_size;
    // 9728 (weights) + 30*64*(8+8+4) = 48128 B -> 4 blocks/SM
    const size_t smem = (size_t)WTOT*4 + (size_t)TSTEPS*BLOCK*(8+8+4);
    cudaFuncSetAttribute(gru_kernel, cudaFuncAttributeMaxDynamicSharedMemorySize, (int)smem);
    gru_kernel<<<NBATCH/BLOCK, BLOCK, smem>>>(
        (const float*)d_in[0],
        (const float*)d_in[1], (const float*)d_in[2],
        (const float*)d_in[3], (const float*)d_in[4],
        (const float*)d_in[5], (const float*)d_in[6],
        (const float*)d_in[7], (const float*)d_in[8],
        (float*)d_out);
}